// round 10
// baseline (speedup 1.0000x reference)
#include <cuda_runtime.h>
#include <cstdint>

// b=2, h=32, n=8192, d=128, e=128, BLOCK=64, num_block=128 -> 8192 tiles.
// Persistent kernel: 1 CTA/SM, 256 threads (8 warps), double-buffered smem,
// cp.async pipeline across tiles. Tile = Q[64x128] @ KV[128x128], decay+residual.

#define QSTRIDE 132    // 128 + 4 pad  (A-frag LDS conflict-free)
#define KVSTRIDE 136   // 128 + 8 pad  (B-frag LDS conflict-free)
#define BUFELEMS (64 * QSTRIDE + 128 * KVSTRIDE)   // 25856 floats = 103424 B
#define SMEM_BYTES (2 * BUFELEMS * 4)              // 206848 B
#define NTILES 8192

__device__ __forceinline__ void stage_tile(float* buf,
                                           const float* __restrict__ q,
                                           const float* __restrict__ kv,
                                           int t, int tid)
{
    const int m  = t & 127;
    const int bh = t >> 7;
    const float* qg  = q  + ((size_t)bh * 8192 + (size_t)m * 64) * 128;
    const float* kvg = kv + ((size_t)bh * 128 + m) * 16384;
    float* Qs  = buf;
    float* KVs = buf + 64 * QSTRIDE;

    #pragma unroll
    for (int i = tid; i < 2048; i += 256) {           // Q: 2048 float4
        int r = i >> 5, c4 = i & 31;
        uint32_t dst = (uint32_t)__cvta_generic_to_shared(Qs + r * QSTRIDE + c4 * 4);
        asm volatile("cp.async.cg.shared.global [%0], [%1], 16;\n"
                     :: "r"(dst), "l"(qg + r * 128 + c4 * 4));
    }
    #pragma unroll
    for (int i = tid; i < 4096; i += 256) {           // KV: 4096 float4
        int r = i >> 5, c4 = i & 31;
        uint32_t dst = (uint32_t)__cvta_generic_to_shared(KVs + r * KVSTRIDE + c4 * 4);
        asm volatile("cp.async.cg.shared.global [%0], [%1], 16;\n"
                     :: "r"(dst), "l"(kvg + r * 128 + c4 * 4));
    }
    asm volatile("cp.async.commit_group;\n" ::: "memory");
}

__global__ __launch_bounds__(256, 1)
void lightning_inter_pipe(const float* __restrict__ q,
                          const float* __restrict__ outp,
                          const float* __restrict__ s,
                          const float* __restrict__ kv,
                          float* __restrict__ out)
{
    extern __shared__ float sm[];
    const int tid    = threadIdx.x;
    const int stride = gridDim.x;

    const int warp = tid >> 5;
    const int lane = tid & 31;
    const int gid  = lane >> 2;     // 0..7
    const int tig  = lane & 3;      // 0..3
    const int m0   = (warp & 3) * 16;   // row quarter of the 64-row tile
    const int n0   = (warp >> 2) * 64;  // col half of the 128-col tile

    int t0 = blockIdx.x;
    if (t0 >= NTILES) return;

    stage_tile(sm, q, kv, t0, tid);     // prologue: tile t0 -> buffer 0
    int buf = 0;

    for (int t = t0; t < NTILES; t += stride) {
        const int tn = t + stride;
        if (tn < NTILES) {
            stage_tile(sm + (buf ^ 1) * BUFELEMS, q, kv, tn, tid);
            asm volatile("cp.async.wait_group 1;\n" ::: "memory");
        } else {
            asm volatile("cp.async.wait_group 0;\n" ::: "memory");
        }
        __syncthreads();

        const float* Qs  = sm + buf * BUFELEMS;
        const float* KVs = Qs + 64 * QSTRIDE;

        float acc[8][4];
        #pragma unroll
        for (int i = 0; i < 8; i++)
            #pragma unroll
            for (int j = 0; j < 4; j++) acc[i][j] = 0.f;

        #pragma unroll
        for (int ks = 0; ks < 16; ks++) {
            const int k0 = ks * 8;
            const float* Ar0 = Qs + (m0 + gid) * QSTRIDE + k0;
            const float* Ar1 = Qs + (m0 + gid + 8) * QSTRIDE + k0;
            uint32_t a0 = __float_as_uint(Ar0[tig]);
            uint32_t a1 = __float_as_uint(Ar1[tig]);
            uint32_t a2 = __float_as_uint(Ar0[tig + 4]);
            uint32_t a3 = __float_as_uint(Ar1[tig + 4]);
            const float* B0 = KVs + (k0 + tig) * KVSTRIDE + n0 + gid;
            const float* B1 = KVs + (k0 + tig + 4) * KVSTRIDE + n0 + gid;
            #pragma unroll
            for (int nt = 0; nt < 8; nt++) {
                uint32_t b0 = __float_as_uint(B0[nt * 8]);
                uint32_t b1 = __float_as_uint(B1[nt * 8]);
                asm volatile(
                    "mma.sync.aligned.m16n8k8.row.col.f32.tf32.tf32.f32 "
                    "{%0,%1,%2,%3},{%4,%5,%6,%7},{%8,%9},{%0,%1,%2,%3};\n"
                    : "+f"(acc[nt][0]), "+f"(acc[nt][1]),
                      "+f"(acc[nt][2]), "+f"(acc[nt][3])
                    : "r"(a0), "r"(a1), "r"(a2), "r"(a3), "r"(b0), "r"(b1));
            }
        }

        // ---- Epilogue: out = output_in + exp(-s*(pos+1)) * acc (streaming, .cs) ----
        const int m  = t & 127;
        const int bh = t >> 7;
        const int h  = bh & 31;
        const size_t row0 = ((size_t)bh * 8192 + (size_t)m * 64) * 128;
        const float* og   = outp + row0;
        float*       outg = out  + row0;

        const float sh = s[h];
        const int r0 = m0 + gid;
        const int r1 = r0 + 8;
        const float d0 = expf(-sh * (float)(r0 + 1));
        const float d1 = expf(-sh * (float)(r1 + 1));

        #pragma unroll
        for (int nt = 0; nt < 8; nt++) {
            const int col = n0 + nt * 8 + 2 * tig;
            const float2* p0 = (const float2*)(og + (size_t)r0 * 128 + col);
            const float2* p1 = (const float2*)(og + (size_t)r1 * 128 + col);
            float2 v0 = __ldcs(p0);
            float2 v1 = __ldcs(p1);
            v0.x += d0 * acc[nt][0];
            v0.y += d0 * acc[nt][1];
            v1.x += d1 * acc[nt][2];
            v1.y += d1 * acc[nt][3];
            __stcs((float2*)(outg + (size_t)r0 * 128 + col), v0);
            __stcs((float2*)(outg + (size_t)r1 * 128 + col), v1);
        }

        __syncthreads();   // all warps done reading buf before it is refilled
        buf ^= 1;
    }
}

extern "C" void kernel_launch(void* const* d_in, const int* in_sizes, int n_in,
                              void* d_out, int out_size)
{
    const float* q    = (const float*)d_in[0]; // [2,32,8192,128]
    const float* outp = (const float*)d_in[1]; // [2,32,8192,128]
    const float* s    = (const float*)d_in[2]; // [32]
    const float* kv   = (const float*)d_in[3]; // [2,32,128,128,128]
    float* out = (float*)d_out;

    static int sms = 0;
    if (sms == 0) {
        int dev = 0;
        cudaGetDevice(&dev);
        cudaDeviceGetAttribute(&sms, cudaDevAttrMultiProcessorCount, dev);
        if (sms <= 0) sms = 148;
        cudaFuncSetAttribute(lightning_inter_pipe,
                             cudaFuncAttributeMaxDynamicSharedMemorySize, SMEM_BYTES);
    }

    lightning_inter_pipe<<<sms, 256, SMEM_BYTES>>>(q, outp, s, kv, out);
}

// round 16
// speedup vs baseline: 1.6979x; 1.6979x over previous
#include <cuda_runtime.h>
#include <cuda_fp16.h>
#include <cstdint>

// b=2,h=32,n=8192,d=128,e=128,BLOCK=64,num_block=128 -> 8192 tiles, 1 CTA each.
// Tile: out[64x128] = output_in + decay(row) * (Q[64x128] @ KV[128x128]).
// fp16 smem staging (XOR-swizzled 16B chunks) + ldmatrix + mma.m16n8k16, fp32 accum.
// 48 KB smem/CTA (== default dyn-smem limit, no attribute call needed),
// <=128 regs -> 4 CTAs/SM for load/compute overlap across independent CTAs.

#define SMEM_BYTES 49152

__device__ __forceinline__ int swz(int row, int chunk) {
    // position of a 16B chunk within a 256B (128-half) row
    return (chunk & 8) | ((chunk ^ row) & 7);
}

__global__ __launch_bounds__(128, 4)
void lightning_inter_fp16(const float* __restrict__ q,
                          const float* __restrict__ outp,
                          const float* __restrict__ s,
                          const float* __restrict__ kv,
                          float* __restrict__ out)
{
    extern __shared__ __half sm[];
    __half* Qs  = sm;          // 64 rows  x 128 halves (256B/row)
    __half* KVs = sm + 8192;   // 128 rows x 128 halves

    const int c  = blockIdx.x;
    const int m  = c & 127;
    const int bh = c >> 7;
    const int h  = bh & 31;

    const size_t row0 = ((size_t)bh * 8192 + (size_t)m * 64) * 128;
    const float* qg   = q    + row0;
    const float* og   = outp + row0;
    float*       outg = out  + row0;
    const float* kvg  = kv + ((size_t)bh * 128 + m) * 16384;

    const int tid = threadIdx.x;
    const uint32_t qbase  = (uint32_t)__cvta_generic_to_shared(Qs);
    const uint32_t kvbase = (uint32_t)__cvta_generic_to_shared(KVs);

    // ---- Stage Q (2048 float4) and KV (4096 float4): LDG.cs fp32 -> cvt fp16 -> STS ----
    #pragma unroll
    for (int j0 = 0; j0 < 16; j0 += 8) {               // Q
        float4 v[8];
        #pragma unroll
        for (int j = 0; j < 8; j++) {
            int u = tid + 128 * (j0 + j);
            v[j] = __ldcs((const float4*)(qg + (u >> 5) * 128 + (u & 31) * 4));
        }
        #pragma unroll
        for (int j = 0; j < 8; j++) {
            int u = tid + 128 * (j0 + j);
            int r = u >> 5, c4 = u & 31;
            uint32_t addr = qbase + r * 256 + swz(r, c4 >> 1) * 16 + (c4 & 1) * 8;
            __half2 h0 = __floats2half2_rn(v[j].x, v[j].y);
            __half2 h1 = __floats2half2_rn(v[j].z, v[j].w);
            asm volatile("st.shared.v2.b32 [%0], {%1,%2};\n"
                         :: "r"(addr), "r"(*(uint32_t*)&h0), "r"(*(uint32_t*)&h1));
        }
    }
    #pragma unroll
    for (int j0 = 0; j0 < 32; j0 += 8) {               // KV
        float4 v[8];
        #pragma unroll
        for (int j = 0; j < 8; j++) {
            int u = tid + 128 * (j0 + j);
            v[j] = __ldcs((const float4*)(kvg + (u >> 5) * 128 + (u & 31) * 4));
        }
        #pragma unroll
        for (int j = 0; j < 8; j++) {
            int u = tid + 128 * (j0 + j);
            int r = u >> 5, c4 = u & 31;
            uint32_t addr = kvbase + r * 256 + swz(r, c4 >> 1) * 16 + (c4 & 1) * 8;
            __half2 h0 = __floats2half2_rn(v[j].x, v[j].y);
            __half2 h1 = __floats2half2_rn(v[j].z, v[j].w);
            asm volatile("st.shared.v2.b32 [%0], {%1,%2};\n"
                         :: "r"(addr), "r"(*(uint32_t*)&h0), "r"(*(uint32_t*)&h1));
        }
    }
    __syncthreads();

    // ---- fp16 MMA: warp owns rows [warp*16, +16), all 128 cols ----
    const int warp = tid >> 5;
    const int lane = tid & 31;
    const int gid  = lane >> 2;
    const int tig  = lane & 3;
    const int m0   = warp * 16;

    const int lrow7 = lane & 7;
    const int lbit8 = ((lane >> 3) & 1) * 8;
    const int lhi   = lane >> 4;            // 0/1: selects k-chunk (A) / n-chunk (B)
    const int arow  = m0 + lrow7 + lbit8;   // A ldmatrix row for this lane

    float acc[16][4];
    #pragma unroll
    for (int i = 0; i < 16; i++)
        #pragma unroll
        for (int j = 0; j < 4; j++) acc[i][j] = 0.f;

    #pragma unroll
    for (int ks = 0; ks < 8; ks++) {        // K in steps of 16
        // A fragment: ldmatrix.x4 (m16 x k16)
        uint32_t a0, a1, a2, a3;
        {
            int kchunk = 2 * ks + lhi;
            uint32_t aaddr = qbase + arow * 256 + swz(arow, kchunk) * 16;
            asm volatile("ldmatrix.sync.aligned.m8n8.x4.shared.b16 {%0,%1,%2,%3}, [%4];\n"
                         : "=r"(a0), "=r"(a1), "=r"(a2), "=r"(a3) : "r"(aaddr));
        }
        const int krow = 16 * ks + lrow7 + lbit8;   // B ldmatrix row for this lane
        #pragma unroll
        for (int nt2 = 0; nt2 < 8; nt2++) {         // two n-tiles (8 cols each) per ldmatrix
            uint32_t b0, b1, b2, b3;
            int nchunk = 2 * nt2 + lhi;
            uint32_t baddr = kvbase + krow * 256 + swz(krow, nchunk) * 16;
            asm volatile("ldmatrix.sync.aligned.m8n8.x4.trans.shared.b16 {%0,%1,%2,%3}, [%4];\n"
                         : "=r"(b0), "=r"(b1), "=r"(b2), "=r"(b3) : "r"(baddr));
            const int nt = 2 * nt2;
            asm volatile(
                "mma.sync.aligned.m16n8k16.row.col.f32.f16.f16.f32 "
                "{%0,%1,%2,%3},{%4,%5,%6,%7},{%8,%9},{%0,%1,%2,%3};\n"
                : "+f"(acc[nt][0]), "+f"(acc[nt][1]), "+f"(acc[nt][2]), "+f"(acc[nt][3])
                : "r"(a0), "r"(a1), "r"(a2), "r"(a3), "r"(b0), "r"(b1));
            asm volatile(
                "mma.sync.aligned.m16n8k16.row.col.f32.f16.f16.f32 "
                "{%0,%1,%2,%3},{%4,%5,%6,%7},{%8,%9},{%0,%1,%2,%3};\n"
                : "+f"(acc[nt+1][0]), "+f"(acc[nt+1][1]), "+f"(acc[nt+1][2]), "+f"(acc[nt+1][3])
                : "r"(a0), "r"(a1), "r"(a2), "r"(a3), "r"(b2), "r"(b3));
        }
    }

    // ---- Epilogue: out = output_in + exp(-s*(pos+1)) * acc (streaming) ----
    const float sh = s[h];
    const int r0 = m0 + gid;
    const int r1 = r0 + 8;
    const float d0 = expf(-sh * (float)(r0 + 1));
    const float d1 = expf(-sh * (float)(r1 + 1));

    #pragma unroll
    for (int nt = 0; nt < 16; nt++) {
        const int col = nt * 8 + 2 * tig;
        float2 v0 = __ldcs((const float2*)(og + (size_t)r0 * 128 + col));
        float2 v1 = __ldcs((const float2*)(og + (size_t)r1 * 128 + col));
        v0.x += d0 * acc[nt][0];
        v0.y += d0 * acc[nt][1];
        v1.x += d1 * acc[nt][2];
        v1.y += d1 * acc[nt][3];
        __stcs((float2*)(outg + (size_t)r0 * 128 + col), v0);
        __stcs((float2*)(outg + (size_t)r1 * 128 + col), v1);
    }
}

extern "C" void kernel_launch(void* const* d_in, const int* in_sizes, int n_in,
                              void* d_out, int out_size)
{
    const float* q    = (const float*)d_in[0]; // [2,32,8192,128]
    const float* outp = (const float*)d_in[1]; // [2,32,8192,128]
    const float* s    = (const float*)d_in[2]; // [32]
    const float* kv   = (const float*)d_in[3]; // [2,32,128,128,128]
    float* out = (float*)d_out;

    // 49152 B == default dynamic-smem limit: no cudaFuncSetAttribute needed,
    // and nothing but the launch itself touches the stream (graph-capture safe).
    lightning_inter_fp16<<<8192, 128, SMEM_BYTES>>>(q, outp, s, kv, out);
}